// round 6
// baseline (speedup 1.0000x reference)
#include <cuda_runtime.h>
#include <math.h>

#define SQ   2048
#define DIM  1024
#define NH   16
#define HD   64
#define FACT 16

// ---- scratch (device globals: the sanctioned no-alloc scratch path) ----
__device__ float g_Q[NH * SQ * HD];              // 8 MB  [h][s][hd]
__device__ float g_K[NH * SQ * HD];              // 8 MB
__device__ float g_V[NH * SQ * HD];              // 8 MB
__device__ float g_vsum[NH * HD];
__device__ float g_attn[SQ * DIM];               // 8 MB  [s][d]
__device__ float g_WT[4 * DIM * DIM];            // 16 MB transposed weights

// ============================================================
// helpers
// ============================================================
__device__ __forceinline__ unsigned f2tf(float f) {
    unsigned u;
    asm("cvt.rna.tf32.f32 %0, %1;" : "=r"(u) : "f"(f));
    return u;
}

__device__ __forceinline__ void mma_tf32(float* c, const unsigned* a, const unsigned* b) {
    asm volatile(
        "mma.sync.aligned.m16n8k8.row.col.f32.tf32.tf32.f32 "
        "{%0,%1,%2,%3}, {%4,%5,%6,%7}, {%8,%9}, {%0,%1,%2,%3};"
        : "+f"(c[0]), "+f"(c[1]), "+f"(c[2]), "+f"(c[3])
        : "r"(a[0]), "r"(a[1]), "r"(a[2]), "r"(a[3]),
          "r"(b[0]), "r"(b[1]));
}

// ============================================================
// 1024x1024 fp32 transpose (for weights -> NT form)
// ============================================================
__global__ __launch_bounds__(256) void transpose1024(
    const float* __restrict__ S, float* __restrict__ D)
{
    __shared__ float tile[32][33];
    int x = blockIdx.x * 32 + threadIdx.x;
    int y = blockIdx.y * 32 + threadIdx.y;
#pragma unroll
    for (int j = 0; j < 32; j += 8)
        tile[threadIdx.y + j][threadIdx.x] = S[(size_t)(y + j) * DIM + x];
    __syncthreads();
    x = blockIdx.y * 32 + threadIdx.x;
    y = blockIdx.x * 32 + threadIdx.y;
#pragma unroll
    for (int j = 0; j < 32; j += 8)
        D[(size_t)(y + j) * DIM + x] = tile[threadIdx.x][threadIdx.y + j];
}

// ============================================================
// Unified NT 3xTF32 tensor-core GEMM (fp32-accurate) for the
// dense projections. Same as R4 (verified correct).
// ============================================================
#define BKT 32
#define SMS 36
#define SM_PLANE (128 * SMS)
#define SMEM_BYTES (4 * SM_PLANE * 4)

__global__ __launch_bounds__(256) void nt_tf32x3_gemm(
    const float* __restrict__ A, const float* __restrict__ B,
    const float* __restrict__ bias, float* __restrict__ C,
    int K, int lda, int ldb, int ldc,
    float alpha, int remap,
    long strA, long strB, long strC)
{
    extern __shared__ unsigned sm[];
    unsigned* AsH = sm;
    unsigned* AsL = sm + SM_PLANE;
    unsigned* BsH = sm + 2 * SM_PLANE;
    unsigned* BsL = sm + 3 * SM_PLANE;

    A += (size_t)blockIdx.z * strA;
    B += (size_t)blockIdx.z * strB;
    C += (size_t)blockIdx.z * strC;

    const int tid  = threadIdx.x;
    const int lane = tid & 31;
    const int wid  = tid >> 5;
    const int wm   = (wid >> 2) * 64;
    const int wn   = (wid & 3) * 32;
    const int g    = lane >> 2;
    const int t    = lane & 3;

    const int m0 = blockIdx.y * 128;
    const int n0 = blockIdx.x * 128;

    float acc[4][4][4];
#pragma unroll
    for (int mt = 0; mt < 4; mt++)
#pragma unroll
        for (int nt = 0; nt < 4; nt++)
#pragma unroll
            for (int e = 0; e < 4; e++) acc[mt][nt][e] = 0.0f;

    for (int k0 = 0; k0 < K; k0 += BKT) {
#pragma unroll
        for (int i = 0; i < 4; i++) {
            const int idx = tid + i * 256;
            const int row = idx >> 3;
            const int kc  = (idx & 7) << 2;
            const int so  = row * SMS + kc;

            float4 av = *(const float4*)&A[(size_t)(m0 + row) * lda + k0 + kc];
            uint4 ah, al;
            ah.x = f2tf(av.x); al.x = f2tf(av.x - __uint_as_float(ah.x));
            ah.y = f2tf(av.y); al.y = f2tf(av.y - __uint_as_float(ah.y));
            ah.z = f2tf(av.z); al.z = f2tf(av.z - __uint_as_float(ah.z));
            ah.w = f2tf(av.w); al.w = f2tf(av.w - __uint_as_float(ah.w));
            *(uint4*)&AsH[so] = ah;
            *(uint4*)&AsL[so] = al;

            float4 bv = *(const float4*)&B[(size_t)(n0 + row) * ldb + k0 + kc];
            uint4 bh, bl;
            bh.x = f2tf(bv.x); bl.x = f2tf(bv.x - __uint_as_float(bh.x));
            bh.y = f2tf(bv.y); bl.y = f2tf(bv.y - __uint_as_float(bh.y));
            bh.z = f2tf(bv.z); bl.z = f2tf(bv.z - __uint_as_float(bh.z));
            bh.w = f2tf(bv.w); bl.w = f2tf(bv.w - __uint_as_float(bh.w));
            *(uint4*)&BsH[so] = bh;
            *(uint4*)&BsL[so] = bl;
        }
        __syncthreads();

#pragma unroll
        for (int ks = 0; ks < BKT; ks += 8) {
            unsigned afh[4][4], afl[4][4], bfh[4][2], bfl[4][2];
#pragma unroll
            for (int mt = 0; mt < 4; mt++) {
                const int off = (wm + mt * 16 + g) * SMS + ks + t;
                afh[mt][0] = AsH[off];
                afh[mt][1] = AsH[off + 8 * SMS];
                afh[mt][2] = AsH[off + 4];
                afh[mt][3] = AsH[off + 8 * SMS + 4];
                afl[mt][0] = AsL[off];
                afl[mt][1] = AsL[off + 8 * SMS];
                afl[mt][2] = AsL[off + 4];
                afl[mt][3] = AsL[off + 8 * SMS + 4];
            }
#pragma unroll
            for (int nt = 0; nt < 4; nt++) {
                const int off = (wn + nt * 8 + g) * SMS + ks + t;
                bfh[nt][0] = BsH[off];
                bfh[nt][1] = BsH[off + 4];
                bfl[nt][0] = BsL[off];
                bfl[nt][1] = BsL[off + 4];
            }
#pragma unroll
            for (int mt = 0; mt < 4; mt++)
#pragma unroll
                for (int nt = 0; nt < 4; nt++) {
                    mma_tf32(acc[mt][nt], afl[mt], bfh[nt]);
                    mma_tf32(acc[mt][nt], afh[mt], bfl[nt]);
                    mma_tf32(acc[mt][nt], afh[mt], bfh[nt]);
                }
        }
        __syncthreads();
    }

#pragma unroll
    for (int mt = 0; mt < 4; mt++) {
        const int rowA = m0 + wm + mt * 16 + g;
        const int rowB = rowA + 8;
#pragma unroll
        for (int nt = 0; nt < 4; nt++) {
            const int col = n0 + wn + nt * 8 + 2 * t;
            float bx = 0.0f, by = 0.0f;
            if (bias) { bx = bias[col]; by = bias[col + 1]; }
            float2 lo, hi;
            lo.x = acc[mt][nt][0] * alpha + bx;
            lo.y = acc[mt][nt][1] * alpha + by;
            hi.x = acc[mt][nt][2] * alpha + bx;
            hi.y = acc[mt][nt][3] * alpha + by;
            if (remap) {
                const int h = col >> 6;
                const int tc = col & 63;
                *(float2*)&C[((size_t)h * SQ + rowA) * HD + tc] = lo;
                *(float2*)&C[((size_t)h * SQ + rowB) * HD + tc] = hi;
            } else {
                *(float2*)&C[(size_t)rowA * ldc + col] = lo;
                *(float2*)&C[(size_t)rowB * ldc + col] = hi;
            }
        }
    }
}

// ============================================================
// Per-head V column sums
// ============================================================
__global__ __launch_bounds__(256) void vsum_kernel()
{
    const int h = blockIdx.x;
    const int t = threadIdx.x & 63;
    const int g = threadIdx.x >> 6;
    const float* Vh = g_V + (size_t)h * SQ * HD;
    float s = 0.0f;
    for (int r = g * 512; r < (g + 1) * 512; ++r)
        s += Vh[(size_t)r * HD + t];
    __shared__ float red[4][64];
    red[g][t] = s;
    __syncthreads();
    if (g == 0)
        g_vsum[h * HD + t] = red[0][t] + red[1][t] + red[2][t] + red[3][t];
}

// ============================================================
// FUSED: scores (3xTF32 mma) + top-16 + sparse softmax + V gather.
// Grid (SQ/128, NH). 256 threads = 8 warps; warp w owns queries
// w*16..w*16+15. Lane (g,t) tracks queries g and g+8 of its warp;
// per k-tile its mma accumulators give it 32 candidates per query
// with k-index = kt*128 + nst*8 + 2t (+1). No scores buffer at all.
// ============================================================
#define FSTR 68
#define FPLANE (128 * FSTR)
#define FSMEM_BYTES (4 * FPLANE * 4)

#define INS16(LV, LI, VAL, IDX)                                        \
    do {                                                               \
        const float _v = (VAL);                                        \
        if (_v > LV[15]) {                                             \
            LV[15] = _v; LI[15] = (IDX);                               \
            _Pragma("unroll")                                          \
            for (int _p = 15; _p >= 1; --_p) {                         \
                if (LV[_p] > LV[_p - 1]) {                             \
                    float _tv = LV[_p]; LV[_p] = LV[_p-1]; LV[_p-1] = _tv; \
                    int   _ti = LI[_p]; LI[_p] = LI[_p-1]; LI[_p-1] = _ti; \
                }                                                      \
            }                                                          \
        }                                                              \
    } while (0)

__device__ __forceinline__ void finalize_query(
    float lv[16], int li[16], int lane, int t,
    const float* __restrict__ Vh, const float* __restrict__ vsum,
    float* __restrict__ outp)
{
    const unsigned FULL = 0xffffffffu;
    float wv[4]; int wi[4];
    float rawmax = -1e30f;

#pragma unroll
    for (int r = 0; r < 16; r++) {
        float v = lv[0]; int ix = li[0];
#pragma unroll
        for (int off = 1; off <= 2; off <<= 1) {
            float ov = __shfl_xor_sync(FULL, v, off);
            int  oix = __shfl_xor_sync(FULL, ix, off);
            if (ov > v || (ov == v && oix < ix)) { v = ov; ix = oix; }
        }
        if (r == 0) rawmax = v;
        if (lv[0] == v && li[0] == ix) {   // exactly one quad lane pops
#pragma unroll
            for (int p = 0; p < 15; p++) { lv[p] = lv[p+1]; li[p] = li[p+1]; }
            lv[15] = -1e30f; li[15] = 0x7fffffff;
        }
        if ((r & 3) == t) { wv[r >> 2] = v; wi[r >> 2] = ix; }
    }

    const float m = fmaxf(rawmax * 0.125f, 0.0f);
    float e[4], z = 0.0f;
#pragma unroll
    for (int j = 0; j < 4; j++) { e[j] = expf(wv[j] * 0.125f - m); z += e[j]; }
    z += __shfl_xor_sync(FULL, z, 1);
    z += __shfl_xor_sync(FULL, z, 2);
    const float e0 = expf(-m);
    const float Z  = z + (float)(SQ - FACT) * e0;
    const float p0 = e0 / Z;
    float wgt[4];
#pragma unroll
    for (int j = 0; j < 4; j++) wgt[j] = e[j] / Z - p0;

    float4 vacc[4];
#pragma unroll
    for (int j = 0; j < 4; j++) {
        float4 s = *(const float4*)&vsum[t * 16 + j * 4];
        vacc[j].x = p0 * s.x; vacc[j].y = p0 * s.y;
        vacc[j].z = p0 * s.z; vacc[j].w = p0 * s.w;
    }
#pragma unroll
    for (int r = 0; r < 16; r++) {
        const int src = (lane & ~3) | (r & 3);
        const float w = __shfl_sync(FULL, wgt[r >> 2], src);
        const int  ix = __shfl_sync(FULL, wi[r >> 2], src);
        const float* vr = Vh + (size_t)ix * HD + t * 16;
#pragma unroll
        for (int j = 0; j < 4; j++) {
            float4 vv = *(const float4*)&vr[j * 4];
            vacc[j].x = fmaf(w, vv.x, vacc[j].x);
            vacc[j].y = fmaf(w, vv.y, vacc[j].y);
            vacc[j].z = fmaf(w, vv.z, vacc[j].z);
            vacc[j].w = fmaf(w, vv.w, vacc[j].w);
        }
    }
#pragma unroll
    for (int j = 0; j < 4; j++)
        *(float4*)&outp[t * 16 + j * 4] = vacc[j];
}

__global__ __launch_bounds__(256) void fused_attend()
{
    extern __shared__ unsigned fsm[];
    unsigned* QsH = fsm;
    unsigned* QsL = fsm + FPLANE;
    unsigned* KsH = fsm + 2 * FPLANE;
    unsigned* KsL = fsm + 3 * FPLANE;

    const int h   = blockIdx.y;
    const int q0  = blockIdx.x * 128;
    const int tid  = threadIdx.x;
    const int lane = tid & 31;
    const int wid  = tid >> 5;
    const int g    = lane >> 2;
    const int t    = lane & 3;
    const int wq   = wid * 16;

    const float* Qh = g_Q + (size_t)h * SQ * HD;
    const float* Kh = g_K + (size_t)h * SQ * HD;
    const float* Vh = g_V + (size_t)h * SQ * HD;

    // stage Q (persistent hi/lo planes)
#pragma unroll
    for (int i = 0; i < 8; i++) {
        const int idx = tid + i * 256;
        const int row = idx >> 4;
        const int c4  = (idx & 15) << 2;
        float4 v = *(const float4*)&Qh[(size_t)(q0 + row) * HD + c4];
        uint4 hi, lo;
        hi.x = f2tf(v.x); lo.x = f2tf(v.x - __uint_as_float(hi.x));
        hi.y = f2tf(v.y); lo.y = f2tf(v.y - __uint_as_float(hi.y));
        hi.z = f2tf(v.z); lo.z = f2tf(v.z - __uint_as_float(hi.z));
        hi.w = f2tf(v.w); lo.w = f2tf(v.w - __uint_as_float(hi.w));
        *(uint4*)&QsH[row * FSTR + c4] = hi;
        *(uint4*)&QsL[row * FSTR + c4] = lo;
    }

    float lv0[16], lv1[16];
    int   li0[16], li1[16];
#pragma unroll
    for (int i = 0; i < 16; i++) {
        lv0[i] = -1e30f; lv1[i] = -1e30f;
        li0[i] = 0x7fffffff; li1[i] = 0x7fffffff;
    }

    for (int kt = 0; kt < 16; kt++) {
        // stage K tile kt (hi/lo)
#pragma unroll
        for (int i = 0; i < 8; i++) {
            const int idx = tid + i * 256;
            const int row = idx >> 4;
            const int c4  = (idx & 15) << 2;
            float4 v = *(const float4*)&Kh[(size_t)(kt * 128 + row) * HD + c4];
            uint4 hi, lo;
            hi.x = f2tf(v.x); lo.x = f2tf(v.x - __uint_as_float(hi.x));
            hi.y = f2tf(v.y); lo.y = f2tf(v.y - __uint_as_float(hi.y));
            hi.z = f2tf(v.z); lo.z = f2tf(v.z - __uint_as_float(hi.z));
            hi.w = f2tf(v.w); lo.w = f2tf(v.w - __uint_as_float(hi.w));
            *(uint4*)&KsH[row * FSTR + c4] = hi;
            *(uint4*)&KsL[row * FSTR + c4] = lo;
        }
        __syncthreads();   // staging (and Q on iter 0) visible

        float acc[16][4];
#pragma unroll
        for (int n = 0; n < 16; n++)
#pragma unroll
            for (int e = 0; e < 4; e++) acc[n][e] = 0.0f;

#pragma unroll
        for (int ks = 0; ks < 8; ks++) {
            const int r0o = (wq + g)     * FSTR + ks * 8 + t;
            const int r1o = (wq + g + 8) * FSTR + ks * 8 + t;
            unsigned aH[4], aL[4];
            aH[0] = QsH[r0o];     aH[1] = QsH[r1o];
            aH[2] = QsH[r0o + 4]; aH[3] = QsH[r1o + 4];
            aL[0] = QsL[r0o];     aL[1] = QsL[r1o];
            aL[2] = QsL[r0o + 4]; aL[3] = QsL[r1o + 4];
#pragma unroll
            for (int nst = 0; nst < 16; nst++) {
                const int bo = (nst * 8 + g) * FSTR + ks * 8 + t;
                unsigned bH[2], bL[2];
                bH[0] = KsH[bo]; bH[1] = KsH[bo + 4];
                bL[0] = KsL[bo]; bL[1] = KsL[bo + 4];
                mma_tf32(acc[nst], aL, bH);
                mma_tf32(acc[nst], aH, bL);
                mma_tf32(acc[nst], aH, bH);
            }
        }
        __syncthreads();   // all warps done reading Ks before restage

        // feed candidates into per-lane top-16 lists (registers only)
#pragma unroll
        for (int nst = 0; nst < 16; nst++) {
            const int kb = kt * 128 + nst * 8 + 2 * t;
            INS16(lv0, li0, acc[nst][0], kb);
            INS16(lv0, li0, acc[nst][1], kb + 1);
            INS16(lv1, li1, acc[nst][2], kb);
            INS16(lv1, li1, acc[nst][3], kb + 1);
        }
    }

    const float* vs = g_vsum + h * HD;
    finalize_query(lv0, li0, lane, t, Vh, vs,
                   g_attn + (size_t)(q0 + wq + g) * DIM + h * HD);
    finalize_query(lv1, li1, lane, t, Vh, vs,
                   g_attn + (size_t)(q0 + wq + g + 8) * DIM + h * HD);
}

// ============================================================
extern "C" void kernel_launch(void* const* d_in, const int* in_sizes, int n_in,
                              void* d_out, int out_size)
{
    const float* x  = (const float*)d_in[0];
    const float* Wq = (const float*)d_in[1];
    const float* bq = (const float*)d_in[2];
    const float* Wk = (const float*)d_in[3];
    const float* bk = (const float*)d_in[4];
    const float* Wv = (const float*)d_in[5];
    const float* bv = (const float*)d_in[6];
    const float* Wo = (const float*)d_in[7];
    const float* bo = (const float*)d_in[8];
    float* out = (float*)d_out;

    float *Qp, *Kp, *Vp, *attnp, *WTp;
    cudaGetSymbolAddress((void**)&Qp,    g_Q);
    cudaGetSymbolAddress((void**)&Kp,    g_K);
    cudaGetSymbolAddress((void**)&Vp,    g_V);
    cudaGetSymbolAddress((void**)&attnp, g_attn);
    cudaGetSymbolAddress((void**)&WTp,   g_WT);

    float* WqT = WTp;
    float* WkT = WTp + (size_t)DIM * DIM;
    float* WvT = WTp + 2 * (size_t)DIM * DIM;
    float* WoT = WTp + 3 * (size_t)DIM * DIM;

    static int smem_set = 0;
    if (!smem_set) {
        cudaFuncSetAttribute(nt_tf32x3_gemm,
                             cudaFuncAttributeMaxDynamicSharedMemorySize,
                             SMEM_BYTES);
        cudaFuncSetAttribute(fused_attend,
                             cudaFuncAttributeMaxDynamicSharedMemorySize,
                             FSMEM_BYTES);
        smem_set = 1;
    }

    dim3 gT(DIM / 32, DIM / 32);
    dim3 bT(32, 8);
    transpose1024<<<gT, bT>>>(Wq, WqT);
    transpose1024<<<gT, bT>>>(Wk, WkT);
    transpose1024<<<gT, bT>>>(Wv, WvT);
    transpose1024<<<gT, bT>>>(Wo, WoT);

    dim3 gProj(DIM / 128, SQ / 128, 1);
    nt_tf32x3_gemm<<<gProj, 256, SMEM_BYTES>>>(x, WqT, bq, Qp, DIM, DIM, DIM, DIM, 1.0f, 1, 0, 0, 0);
    nt_tf32x3_gemm<<<gProj, 256, SMEM_BYTES>>>(x, WkT, bk, Kp, DIM, DIM, DIM, DIM, 1.0f, 1, 0, 0, 0);
    nt_tf32x3_gemm<<<gProj, 256, SMEM_BYTES>>>(x, WvT, bv, Vp, DIM, DIM, DIM, DIM, 1.0f, 1, 0, 0, 0);

    vsum_kernel<<<NH, 256>>>();

    dim3 gF(SQ / 128, NH);   // (16, 16)
    fused_attend<<<gF, 256, FSMEM_BYTES>>>();

    nt_tf32x3_gemm<<<gProj, 256, SMEM_BYTES>>>(attnp, WoT, bo, out, DIM, DIM, DIM, DIM, 1.0f, 0, 0, 0, 0);
}

// round 7
// speedup vs baseline: 1.6534x; 1.6534x over previous
#include <cuda_runtime.h>
#include <cuda_bf16.h>
#include <math.h>

#define SQ   2048
#define DIM  1024
#define NH   16
#define HD   64
#define FACT 16

// ---- scratch (device globals: the sanctioned no-alloc scratch path) ----
__device__ float g_V[NH * SQ * HD];              // 8 MB fp32 [h][s][hd]
__device__ float g_scores[(size_t)NH * SQ * SQ]; // 256 MB [h][q][k]
__device__ float g_vsum[NH * HD];
__device__ float g_attn[SQ * DIM];               // 8 MB fp32 [s][d]

// bf16 split planes
__device__ __nv_bfloat16 g_xh[SQ * DIM],  g_xl[SQ * DIM];        // 4 MB each
__device__ __nv_bfloat16 g_ath[SQ * DIM], g_atl[SQ * DIM];       // 4 MB each
__device__ __nv_bfloat16 g_WTh[4 * DIM * DIM], g_WTl[4 * DIM * DIM]; // 8 MB each
__device__ __nv_bfloat16 g_Qh[NH * SQ * HD], g_Ql[NH * SQ * HD]; // 4 MB each
__device__ __nv_bfloat16 g_Kh[NH * SQ * HD], g_Kl[NH * SQ * HD]; // 4 MB each

// ============================================================
// helpers
// ============================================================
__device__ __forceinline__ void bsplit(float v, __nv_bfloat16& h, __nv_bfloat16& l) {
    h = __float2bfloat16(v);
    l = __float2bfloat16(v - __bfloat162float(h));
}

__device__ __forceinline__ void mma_bf16(float* c, const unsigned* a, const unsigned* b) {
    asm volatile(
        "mma.sync.aligned.m16n8k16.row.col.f32.bf16.bf16.f32 "
        "{%0,%1,%2,%3}, {%4,%5,%6,%7}, {%8,%9}, {%0,%1,%2,%3};"
        : "+f"(c[0]), "+f"(c[1]), "+f"(c[2]), "+f"(c[3])
        : "r"(a[0]), "r"(a[1]), "r"(a[2]), "r"(a[3]),
          "r"(b[0]), "r"(b[1]));
}

// ============================================================
// 1024x1024 transpose + bf16 hi/lo split (weights -> NT planes)
// ============================================================
__global__ __launch_bounds__(256) void transpose_split(
    const float* __restrict__ S,
    __nv_bfloat16* __restrict__ Dh, __nv_bfloat16* __restrict__ Dl)
{
    __shared__ float tile[32][33];
    int x = blockIdx.x * 32 + threadIdx.x;
    int y = blockIdx.y * 32 + threadIdx.y;
#pragma unroll
    for (int j = 0; j < 32; j += 8)
        tile[threadIdx.y + j][threadIdx.x] = S[(size_t)(y + j) * DIM + x];
    __syncthreads();
    x = blockIdx.y * 32 + threadIdx.x;
    y = blockIdx.x * 32 + threadIdx.y;
#pragma unroll
    for (int j = 0; j < 32; j += 8) {
        float v = tile[threadIdx.x][threadIdx.y + j];
        __nv_bfloat16 h, l;
        bsplit(v, h, l);
        Dh[(size_t)(y + j) * DIM + x] = h;
        Dl[(size_t)(y + j) * DIM + x] = l;
    }
}

// ============================================================
// elementwise fp32 -> bf16 hi/lo split
// ============================================================
__global__ __launch_bounds__(256) void split_convert(
    const float* __restrict__ S,
    __nv_bfloat16* __restrict__ Dh, __nv_bfloat16* __restrict__ Dl, int n4)
{
    int i = blockIdx.x * 256 + threadIdx.x;
    if (i >= n4) return;
    float4 v = *(const float4*)&S[i * 4];
    __nv_bfloat16 h0,h1,h2,h3,l0,l1,l2,l3;
    bsplit(v.x, h0, l0); bsplit(v.y, h1, l1);
    bsplit(v.z, h2, l2); bsplit(v.w, h3, l3);
    __nv_bfloat162* ph = (__nv_bfloat162*)&Dh[i * 4];
    __nv_bfloat162* pl = (__nv_bfloat162*)&Dl[i * 4];
    ph[0] = __nv_bfloat162(h0, h1); ph[1] = __nv_bfloat162(h2, h3);
    pl[0] = __nv_bfloat162(l0, l1); pl[1] = __nv_bfloat162(l2, l3);
}

// ============================================================
// NT bf16x3 tensor-core GEMM (fp32-accurate):
//   C[m][n] = alpha * sum_k A[m][k]*B[n][k]  (+ bias[n])
// Operands pre-split into bf16 hi/lo planes in gmem.
// 128x128 tile, BK=64, 8 warps of 64x32 (m16n8k16), cp.async
// double-buffered. mode: 0=fp32 C[row*ldc+col]; 1=fp32 remap to
// [h][row][t]; 2=bf16 split remap to Ch/Cl [h][row][t].
// blockIdx.z batches via strA/strB/strC (elements).
// ============================================================
#define BK   64
#define SWW  36                 // word (2xbf16) stride per row
#define PLANE_W (128 * SWW)     // words per plane
#define GSMEM_BYTES (2 * 4 * PLANE_W * 4)   // 147456

__global__ __launch_bounds__(256) void nt_bf16x3_gemm(
    const __nv_bfloat16* __restrict__ Ah, const __nv_bfloat16* __restrict__ Al,
    const __nv_bfloat16* __restrict__ Bh, const __nv_bfloat16* __restrict__ Bl,
    const float* __restrict__ bias, float* __restrict__ C,
    __nv_bfloat16* __restrict__ Ch, __nv_bfloat16* __restrict__ Cl,
    int K, int lda, int ldb, int ldc,
    float alpha, int mode,
    long strA, long strB, long strC)
{
    extern __shared__ unsigned sm[];
    unsigned sbase = (unsigned)__cvta_generic_to_shared(sm);

    Ah += (size_t)blockIdx.z * strA;  Al += (size_t)blockIdx.z * strA;
    Bh += (size_t)blockIdx.z * strB;  Bl += (size_t)blockIdx.z * strB;

    const int tid  = threadIdx.x;
    const int lane = tid & 31;
    const int wid  = tid >> 5;
    const int wm   = (wid >> 2) * 64;
    const int wn   = (wid & 3) * 32;
    const int g    = lane >> 2;
    const int t    = lane & 3;

    const int m0 = blockIdx.y * 128;
    const int n0 = blockIdx.x * 128;

    const __nv_bfloat16* gp0 = Ah + (size_t)m0 * lda;
    const __nv_bfloat16* gp1 = Al + (size_t)m0 * lda;
    const __nv_bfloat16* gp2 = Bh + (size_t)n0 * ldb;
    const __nv_bfloat16* gp3 = Bl + (size_t)n0 * ldb;

    float acc[4][4][4];
#pragma unroll
    for (int mt = 0; mt < 4; mt++)
#pragma unroll
        for (int nt = 0; nt < 4; nt++)
#pragma unroll
            for (int e = 0; e < 4; e++) acc[mt][nt][e] = 0.0f;

    const int T = K / BK;

    // ---- staging lambda-ish macro: tile -> buffer buf at k-offset k0 ----
#define STAGE(BUF, K0)                                                        \
    do {                                                                      \
        const __nv_bfloat16* gps[4] = {gp0, gp1, gp2, gp3};                   \
        _Pragma("unroll")                                                     \
        for (int p = 0; p < 4; p++) {                                         \
            const int ld = (p < 2) ? lda : ldb;                               \
            const unsigned sb = sbase + ((BUF) * 4 + p) * (PLANE_W * 4);      \
            _Pragma("unroll")                                                 \
            for (int i = 0; i < 4; i++) {                                     \
                const int c   = tid + i * 256;                                \
                const int row = c >> 3;                                       \
                const int c8  = c & 7;                                        \
                const __nv_bfloat16* src = gps[p] + (size_t)row * ld + (K0) + c8 * 8; \
                const unsigned dst = sb + row * (SWW * 4) + c8 * 16;          \
                asm volatile("cp.async.cg.shared.global [%0], [%1], 16;"      \
                             :: "r"(dst), "l"(src));                          \
            }                                                                 \
        }                                                                     \
        asm volatile("cp.async.commit_group;");                               \
    } while (0)

    STAGE(0, 0);

    for (int tt = 0; tt < T; tt++) {
        if (tt + 1 < T) {
            STAGE((tt + 1) & 1, (tt + 1) * BK);
            asm volatile("cp.async.wait_group 1;");
        } else {
            asm volatile("cp.async.wait_group 0;");
        }
        __syncthreads();

        const unsigned* AH = sm + ((tt & 1) * 4 + 0) * PLANE_W;
        const unsigned* AL = sm + ((tt & 1) * 4 + 1) * PLANE_W;
        const unsigned* BH = sm + ((tt & 1) * 4 + 2) * PLANE_W;
        const unsigned* BL = sm + ((tt & 1) * 4 + 3) * PLANE_W;

#pragma unroll
        for (int ks = 0; ks < 4; ks++) {
            unsigned ah[4][4], al[4][4], bh[4][2], bl[4][2];
#pragma unroll
            for (int mt = 0; mt < 4; mt++) {
                const int w0 = (wm + mt * 16 + g) * SWW + ks * 8 + t;
                const int w1 = w0 + 8 * SWW;
                ah[mt][0] = AH[w0]; ah[mt][1] = AH[w1];
                ah[mt][2] = AH[w0 + 4]; ah[mt][3] = AH[w1 + 4];
                al[mt][0] = AL[w0]; al[mt][1] = AL[w1];
                al[mt][2] = AL[w0 + 4]; al[mt][3] = AL[w1 + 4];
            }
#pragma unroll
            for (int nt = 0; nt < 4; nt++) {
                const int wb = (wn + nt * 8 + g) * SWW + ks * 8 + t;
                bh[nt][0] = BH[wb]; bh[nt][1] = BH[wb + 4];
                bl[nt][0] = BL[wb]; bl[nt][1] = BL[wb + 4];
            }
#pragma unroll
            for (int mt = 0; mt < 4; mt++)
#pragma unroll
                for (int nt = 0; nt < 4; nt++) {
                    mma_bf16(acc[mt][nt], al[mt], bh[nt]);
                    mma_bf16(acc[mt][nt], ah[mt], bl[nt]);
                    mma_bf16(acc[mt][nt], ah[mt], bh[nt]);
                }
        }
        __syncthreads();
    }

    // ---- epilogue ----
#pragma unroll
    for (int mt = 0; mt < 4; mt++) {
        const int rowA = m0 + wm + mt * 16 + g;
        const int rowB = rowA + 8;
#pragma unroll
        for (int nt = 0; nt < 4; nt++) {
            const int col = n0 + wn + nt * 8 + 2 * t;
            float bx = 0.0f, by = 0.0f;
            if (bias) { bx = bias[col]; by = bias[col + 1]; }
            float lox = acc[mt][nt][0] * alpha + bx;
            float loy = acc[mt][nt][1] * alpha + by;
            float hix = acc[mt][nt][2] * alpha + bx;
            float hiy = acc[mt][nt][3] * alpha + by;
            if (mode == 0) {
                float* Cz = C + (size_t)blockIdx.z * strC;
                *(float2*)&Cz[(size_t)rowA * ldc + col] = make_float2(lox, loy);
                *(float2*)&Cz[(size_t)rowB * ldc + col] = make_float2(hix, hiy);
            } else if (mode == 1) {
                const int h = col >> 6, tc = col & 63;
                *(float2*)&C[((size_t)h * SQ + rowA) * HD + tc] = make_float2(lox, loy);
                *(float2*)&C[((size_t)h * SQ + rowB) * HD + tc] = make_float2(hix, hiy);
            } else {
                const int h = col >> 6, tc = col & 63;
                __nv_bfloat16 h0,h1,h2,h3,l0,l1,l2,l3;
                bsplit(lox, h0, l0); bsplit(loy, h1, l1);
                bsplit(hix, h2, l2); bsplit(hiy, h3, l3);
                *(__nv_bfloat162*)&Ch[((size_t)h * SQ + rowA) * HD + tc] = __nv_bfloat162(h0, h1);
                *(__nv_bfloat162*)&Cl[((size_t)h * SQ + rowA) * HD + tc] = __nv_bfloat162(l0, l1);
                *(__nv_bfloat162*)&Ch[((size_t)h * SQ + rowB) * HD + tc] = __nv_bfloat162(h2, h3);
                *(__nv_bfloat162*)&Cl[((size_t)h * SQ + rowB) * HD + tc] = __nv_bfloat162(l2, l3);
            }
        }
    }
#undef STAGE
}

// ============================================================
// Per-head V column sums
// ============================================================
__global__ __launch_bounds__(256) void vsum_kernel()
{
    const int h = blockIdx.x;
    const int t = threadIdx.x & 63;
    const int g = threadIdx.x >> 6;
    const float* Vh = g_V + (size_t)h * SQ * HD;
    float s = 0.0f;
    for (int r = g * 512; r < (g + 1) * 512; ++r)
        s += Vh[(size_t)r * HD + t];
    __shared__ float red[4][64];
    red[g][t] = s;
    __syncthreads();
    if (g == 0)
        g_vsum[h * HD + t] = red[0][t] + red[1][t] + red[2][t] + red[3][t];
}

// ============================================================
// Top-16 + sparse softmax + PV gather. One warp per (h, q).
// (unchanged from the 966us kernel)
// ============================================================
__global__ __launch_bounds__(128) void topk_attend()
{
    const unsigned FULL = 0xffffffffu;
    const int gwarp = (blockIdx.x * 128 + threadIdx.x) >> 5;
    const int lane  = threadIdx.x & 31;
    const int h = gwarp >> 11;
    const int q = gwarp & 2047;

    const float* row = g_scores + ((size_t)h * SQ + q) * SQ;

    float lv[16];
    int   li[16];
#pragma unroll
    for (int i = 0; i < 16; i++) { lv[i] = -1e30f; li[i] = 0; }

#pragma unroll 4
    for (int c = 0; c < 16; c++) {
        const int base = c * 128 + lane * 4;
        float4 v4 = *(const float4*)&row[base];
        float vals[4] = {v4.x, v4.y, v4.z, v4.w};
#pragma unroll
        for (int j = 0; j < 4; j++) {
            const float val = vals[j];
            if (val > lv[15]) {
                lv[15] = val; li[15] = base + j;
#pragma unroll
                for (int p = 15; p >= 1; --p) {
                    if (lv[p] > lv[p - 1]) {
                        float tv = lv[p]; lv[p] = lv[p - 1]; lv[p - 1] = tv;
                        int   ti = li[p]; li[p] = li[p - 1]; li[p - 1] = ti;
                    }
                }
            }
        }
    }

    float fv = -1e30f;
    int   fi = 0;
    for (int r = 0; r < 16; r++) {
        float bv = lv[0]; int bi = li[0]; int bl = lane;
#pragma unroll
        for (int off = 16; off > 0; off >>= 1) {
            float ov = __shfl_down_sync(FULL, bv, off);
            int   oi = __shfl_down_sync(FULL, bi, off);
            int   ol = __shfl_down_sync(FULL, bl, off);
            if (ov > bv) { bv = ov; bi = oi; bl = ol; }
        }
        bv = __shfl_sync(FULL, bv, 0);
        bi = __shfl_sync(FULL, bi, 0);
        bl = __shfl_sync(FULL, bl, 0);
        if (lane == bl) {
#pragma unroll
            for (int p = 0; p < 15; p++) { lv[p] = lv[p + 1]; li[p] = li[p + 1]; }
            lv[15] = -1e30f;
        }
        if (lane == r) { fv = bv; fi = bi; }
    }

    float m = __shfl_sync(FULL, fv, 0);
    m = fmaxf(m, 0.0f);
    float e = (lane < 16) ? expf(fv - m) : 0.0f;
    float z = e;
#pragma unroll
    for (int off = 16; off > 0; off >>= 1)
        z += __shfl_xor_sync(FULL, z, off);
    const float e0 = expf(-m);
    const float Z  = z + (float)(SQ - FACT) * e0;
    const float p0 = e0 / Z;
    const float w  = e / Z - p0;

    const float* Vh = g_V + (size_t)h * SQ * HD;
    float acc0 = p0 * g_vsum[h * HD + lane];
    float acc1 = p0 * g_vsum[h * HD + lane + 32];
#pragma unroll
    for (int i = 0; i < 16; i++) {
        const float wi  = __shfl_sync(FULL, w,  i);
        const int   idx = __shfl_sync(FULL, fi, i);
        const float* vr = Vh + (size_t)idx * HD;
        acc0 = fmaf(wi, vr[lane],      acc0);
        acc1 = fmaf(wi, vr[lane + 32], acc1);
    }
    float* o = g_attn + (size_t)q * DIM + h * HD;
    o[lane]      = acc0;
    o[lane + 32] = acc1;
}

// ============================================================
extern "C" void kernel_launch(void* const* d_in, const int* in_sizes, int n_in,
                              void* d_out, int out_size)
{
    const float* x  = (const float*)d_in[0];
    const float* Wq = (const float*)d_in[1];
    const float* bq = (const float*)d_in[2];
    const float* Wk = (const float*)d_in[3];
    const float* bk = (const float*)d_in[4];
    const float* Wv = (const float*)d_in[5];
    const float* bv = (const float*)d_in[6];
    const float* Wo = (const float*)d_in[7];
    const float* bo = (const float*)d_in[8];
    float* out = (float*)d_out;

    float *Vp, *attnp, *scoresp;
    __nv_bfloat16 *xh, *xl, *ath, *atl, *WTh, *WTl, *Qh, *Ql, *Kh, *Kl;
    cudaGetSymbolAddress((void**)&Vp,      g_V);
    cudaGetSymbolAddress((void**)&attnp,   g_attn);
    cudaGetSymbolAddress((void**)&scoresp, g_scores);
    cudaGetSymbolAddress((void**)&xh,  g_xh);  cudaGetSymbolAddress((void**)&xl,  g_xl);
    cudaGetSymbolAddress((void**)&ath, g_ath); cudaGetSymbolAddress((void**)&atl, g_atl);
    cudaGetSymbolAddress((void**)&WTh, g_WTh); cudaGetSymbolAddress((void**)&WTl, g_WTl);
    cudaGetSymbolAddress((void**)&Qh,  g_Qh);  cudaGetSymbolAddress((void**)&Ql,  g_Ql);
    cudaGetSymbolAddress((void**)&Kh,  g_Kh);  cudaGetSymbolAddress((void**)&Kl,  g_Kl);

    static int smem_set = 0;
    if (!smem_set) {
        cudaFuncSetAttribute(nt_bf16x3_gemm,
                             cudaFuncAttributeMaxDynamicSharedMemorySize,
                             GSMEM_BYTES);
        smem_set = 1;
    }

    const size_t DD = (size_t)DIM * DIM;

    dim3 gT(DIM / 32, DIM / 32);
    dim3 bT(32, 8);
    transpose_split<<<gT, bT>>>(Wq, WTh,          WTl);
    transpose_split<<<gT, bT>>>(Wk, WTh + DD,     WTl + DD);
    transpose_split<<<gT, bT>>>(Wv, WTh + 2 * DD, WTl + 2 * DD);
    transpose_split<<<gT, bT>>>(Wo, WTh + 3 * DD, WTl + 3 * DD);

    split_convert<<<(SQ * DIM / 4 + 255) / 256, 256>>>(x, xh, xl, SQ * DIM / 4);

    dim3 gProj(DIM / 128, SQ / 128, 1);
    // Q projection -> bf16 split planes
    nt_bf16x3_gemm<<<gProj, 256, GSMEM_BYTES>>>(
        xh, xl, WTh, WTl, bq, nullptr, Qh, Ql,
        DIM, DIM, DIM, DIM, 1.0f, 2, 0, 0, 0);
    // K projection -> bf16 split planes
    nt_bf16x3_gemm<<<gProj, 256, GSMEM_BYTES>>>(
        xh, xl, WTh + DD, WTl + DD, bk, nullptr, Kh, Kl,
        DIM, DIM, DIM, DIM, 1.0f, 2, 0, 0, 0);
    // V projection -> fp32 remap
    nt_bf16x3_gemm<<<gProj, 256, GSMEM_BYTES>>>(
        xh, xl, WTh + 2 * DD, WTl + 2 * DD, bv, Vp, nullptr, nullptr,
        DIM, DIM, DIM, DIM, 1.0f, 1, 0, 0, 0);

    vsum_kernel<<<NH, 256>>>();

    // scores: per-head NT GEMM over bf16 planes
    dim3 gSc(SQ / 128, SQ / 128, NH);
    nt_bf16x3_gemm<<<gSc, 256, GSMEM_BYTES>>>(
        Qh, Ql, Kh, Kl, nullptr, scoresp, nullptr, nullptr,
        HD, HD, HD, SQ, 0.125f, 0,
        (long)SQ * HD, (long)SQ * HD, (long)SQ * SQ);

    topk_attend<<<(NH * SQ) / 4, 128>>>();

    split_convert<<<(SQ * DIM / 4 + 255) / 256, 256>>>(attnp, ath, atl, SQ * DIM / 4);

    // output projection -> fp32 out
    nt_bf16x3_gemm<<<gProj, 256, GSMEM_BYTES>>>(
        ath, atl, WTh + 3 * DD, WTl + 3 * DD, bo, out, nullptr, nullptr,
        DIM, DIM, DIM, DIM, 1.0f, 0, 0, 0, 0);
}

// round 8
// speedup vs baseline: 1.6558x; 1.0014x over previous
#include <cuda_runtime.h>
#include <cuda_bf16.h>
#include <math.h>

#define SQ   2048
#define DIM  1024
#define NH   16
#define HD   64
#define FACT 16

// ---- scratch (device globals: the sanctioned no-alloc scratch path) ----
__device__ float g_V[NH * SQ * HD];              // 8 MB fp32 [h][s][hd]
__device__ float g_scores[(size_t)NH * SQ * SQ]; // 256 MB [h][q][k]
__device__ float g_vsum[NH * HD];
__device__ float g_attn[SQ * DIM];               // 8 MB fp32 [s][d]

// bf16 split planes
__device__ __nv_bfloat16 g_xh[SQ * DIM],  g_xl[SQ * DIM];        // 4 MB each
__device__ __nv_bfloat16 g_ath[SQ * DIM], g_atl[SQ * DIM];       // 4 MB each
__device__ __nv_bfloat16 g_WTh[4 * DIM * DIM], g_WTl[4 * DIM * DIM]; // 8 MB each
__device__ __nv_bfloat16 g_Qh[NH * SQ * HD], g_Ql[NH * SQ * HD]; // 4 MB each
__device__ __nv_bfloat16 g_Kh[NH * SQ * HD], g_Kl[NH * SQ * HD]; // 4 MB each

// ============================================================
// helpers
// ============================================================
__device__ __forceinline__ void bsplit(float v, __nv_bfloat16& h, __nv_bfloat16& l) {
    h = __float2bfloat16(v);
    l = __float2bfloat16(v - __bfloat162float(h));
}

__device__ __forceinline__ void mma_bf16(float* c, const unsigned* a, const unsigned* b) {
    asm volatile(
        "mma.sync.aligned.m16n8k16.row.col.f32.bf16.bf16.f32 "
        "{%0,%1,%2,%3}, {%4,%5,%6,%7}, {%8,%9}, {%0,%1,%2,%3};"
        : "+f"(c[0]), "+f"(c[1]), "+f"(c[2]), "+f"(c[3])
        : "r"(a[0]), "r"(a[1]), "r"(a[2]), "r"(a[3]),
          "r"(b[0]), "r"(b[1]));
}

// ============================================================
// 1024x1024 transpose + bf16 hi/lo split (weights -> NT planes)
// ============================================================
__global__ __launch_bounds__(256) void transpose_split(
    const float* __restrict__ S,
    __nv_bfloat16* __restrict__ Dh, __nv_bfloat16* __restrict__ Dl)
{
    __shared__ float tile[32][33];
    int x = blockIdx.x * 32 + threadIdx.x;
    int y = blockIdx.y * 32 + threadIdx.y;
#pragma unroll
    for (int j = 0; j < 32; j += 8)
        tile[threadIdx.y + j][threadIdx.x] = S[(size_t)(y + j) * DIM + x];
    __syncthreads();
    x = blockIdx.y * 32 + threadIdx.x;
    y = blockIdx.x * 32 + threadIdx.y;
#pragma unroll
    for (int j = 0; j < 32; j += 8) {
        float v = tile[threadIdx.x][threadIdx.y + j];
        __nv_bfloat16 h, l;
        bsplit(v, h, l);
        Dh[(size_t)(y + j) * DIM + x] = h;
        Dl[(size_t)(y + j) * DIM + x] = l;
    }
}

// ============================================================
// elementwise fp32 -> bf16 hi/lo split
// ============================================================
__global__ __launch_bounds__(256) void split_convert(
    const float* __restrict__ S,
    __nv_bfloat16* __restrict__ Dh, __nv_bfloat16* __restrict__ Dl, int n4)
{
    int i = blockIdx.x * 256 + threadIdx.x;
    if (i >= n4) return;
    float4 v = *(const float4*)&S[i * 4];
    __nv_bfloat16 h0,h1,h2,h3,l0,l1,l2,l3;
    bsplit(v.x, h0, l0); bsplit(v.y, h1, l1);
    bsplit(v.z, h2, l2); bsplit(v.w, h3, l3);
    __nv_bfloat162* ph = (__nv_bfloat162*)&Dh[i * 4];
    __nv_bfloat162* pl = (__nv_bfloat162*)&Dl[i * 4];
    ph[0] = __nv_bfloat162(h0, h1); ph[1] = __nv_bfloat162(h2, h3);
    pl[0] = __nv_bfloat162(l0, l1); pl[1] = __nv_bfloat162(l2, l3);
}

// ============================================================
// NT bf16x3 tensor-core GEMM (fp32-accurate):
//   C[m][n] = alpha * sum_k A[m][k]*B[n][k]  (+ bias[n])
// Operands pre-split into bf16 hi/lo planes in gmem.
// 128x128 tile, BK=64, 8 warps of 64x32 (m16n8k16), cp.async
// double-buffered. mode: 0=fp32 C[row*ldc+col]; 1=fp32 remap to
// [h][row][t]; 2=bf16 split remap to Ch/Cl [h][row][t].
// blockIdx.z batches via strA/strB/strC (elements).
// ============================================================
#define BK   64
#define SWW  36                 // word (2xbf16) stride per row
#define PLANE_W (128 * SWW)     // words per plane
#define GSMEM_BYTES (2 * 4 * PLANE_W * 4)   // 147456

__global__ __launch_bounds__(256) void nt_bf16x3_gemm(
    const __nv_bfloat16* __restrict__ Ah, const __nv_bfloat16* __restrict__ Al,
    const __nv_bfloat16* __restrict__ Bh, const __nv_bfloat16* __restrict__ Bl,
    const float* __restrict__ bias, float* __restrict__ C,
    __nv_bfloat16* __restrict__ Ch, __nv_bfloat16* __restrict__ Cl,
    int K, int lda, int ldb, int ldc,
    float alpha, int mode,
    long strA, long strB, long strC)
{
    extern __shared__ unsigned sm[];
    unsigned sbase = (unsigned)__cvta_generic_to_shared(sm);

    Ah += (size_t)blockIdx.z * strA;  Al += (size_t)blockIdx.z * strA;
    Bh += (size_t)blockIdx.z * strB;  Bl += (size_t)blockIdx.z * strB;

    const int tid  = threadIdx.x;
    const int lane = tid & 31;
    const int wid  = tid >> 5;
    const int wm   = (wid >> 2) * 64;
    const int wn   = (wid & 3) * 32;
    const int g    = lane >> 2;
    const int t    = lane & 3;

    const int m0 = blockIdx.y * 128;
    const int n0 = blockIdx.x * 128;

    const __nv_bfloat16* gp0 = Ah + (size_t)m0 * lda;
    const __nv_bfloat16* gp1 = Al + (size_t)m0 * lda;
    const __nv_bfloat16* gp2 = Bh + (size_t)n0 * ldb;
    const __nv_bfloat16* gp3 = Bl + (size_t)n0 * ldb;

    float acc[4][4][4];
#pragma unroll
    for (int mt = 0; mt < 4; mt++)
#pragma unroll
        for (int nt = 0; nt < 4; nt++)
#pragma unroll
            for (int e = 0; e < 4; e++) acc[mt][nt][e] = 0.0f;

    const int T = K / BK;

    // ---- staging lambda-ish macro: tile -> buffer buf at k-offset k0 ----
#define STAGE(BUF, K0)                                                        \
    do {                                                                      \
        const __nv_bfloat16* gps[4] = {gp0, gp1, gp2, gp3};                   \
        _Pragma("unroll")                                                     \
        for (int p = 0; p < 4; p++) {                                         \
            const int ld = (p < 2) ? lda : ldb;                               \
            const unsigned sb = sbase + ((BUF) * 4 + p) * (PLANE_W * 4);      \
            _Pragma("unroll")                                                 \
            for (int i = 0; i < 4; i++) {                                     \
                const int c   = tid + i * 256;                                \
                const int row = c >> 3;                                       \
                const int c8  = c & 7;                                        \
                const __nv_bfloat16* src = gps[p] + (size_t)row * ld + (K0) + c8 * 8; \
                const unsigned dst = sb + row * (SWW * 4) + c8 * 16;          \
                asm volatile("cp.async.cg.shared.global [%0], [%1], 16;"      \
                             :: "r"(dst), "l"(src));                          \
            }                                                                 \
        }                                                                     \
        asm volatile("cp.async.commit_group;");                               \
    } while (0)

    STAGE(0, 0);

    for (int tt = 0; tt < T; tt++) {
        if (tt + 1 < T) {
            STAGE((tt + 1) & 1, (tt + 1) * BK);
            asm volatile("cp.async.wait_group 1;");
        } else {
            asm volatile("cp.async.wait_group 0;");
        }
        __syncthreads();

        const unsigned* AH = sm + ((tt & 1) * 4 + 0) * PLANE_W;
        const unsigned* AL = sm + ((tt & 1) * 4 + 1) * PLANE_W;
        const unsigned* BH = sm + ((tt & 1) * 4 + 2) * PLANE_W;
        const unsigned* BL = sm + ((tt & 1) * 4 + 3) * PLANE_W;

#pragma unroll
        for (int ks = 0; ks < 4; ks++) {
            unsigned ah[4][4], al[4][4], bh[4][2], bl[4][2];
#pragma unroll
            for (int mt = 0; mt < 4; mt++) {
                const int w0 = (wm + mt * 16 + g) * SWW + ks * 8 + t;
                const int w1 = w0 + 8 * SWW;
                ah[mt][0] = AH[w0]; ah[mt][1] = AH[w1];
                ah[mt][2] = AH[w0 + 4]; ah[mt][3] = AH[w1 + 4];
                al[mt][0] = AL[w0]; al[mt][1] = AL[w1];
                al[mt][2] = AL[w0 + 4]; al[mt][3] = AL[w1 + 4];
            }
#pragma unroll
            for (int nt = 0; nt < 4; nt++) {
                const int wb = (wn + nt * 8 + g) * SWW + ks * 8 + t;
                bh[nt][0] = BH[wb]; bh[nt][1] = BH[wb + 4];
                bl[nt][0] = BL[wb]; bl[nt][1] = BL[wb + 4];
            }
#pragma unroll
            for (int mt = 0; mt < 4; mt++)
#pragma unroll
                for (int nt = 0; nt < 4; nt++) {
                    mma_bf16(acc[mt][nt], al[mt], bh[nt]);
                    mma_bf16(acc[mt][nt], ah[mt], bl[nt]);
                    mma_bf16(acc[mt][nt], ah[mt], bh[nt]);
                }
        }
        __syncthreads();
    }

    // ---- epilogue ----
#pragma unroll
    for (int mt = 0; mt < 4; mt++) {
        const int rowA = m0 + wm + mt * 16 + g;
        const int rowB = rowA + 8;
#pragma unroll
        for (int nt = 0; nt < 4; nt++) {
            const int col = n0 + wn + nt * 8 + 2 * t;
            float bx = 0.0f, by = 0.0f;
            if (bias) { bx = bias[col]; by = bias[col + 1]; }
            float lox = acc[mt][nt][0] * alpha + bx;
            float loy = acc[mt][nt][1] * alpha + by;
            float hix = acc[mt][nt][2] * alpha + bx;
            float hiy = acc[mt][nt][3] * alpha + by;
            if (mode == 0) {
                float* Cz = C + (size_t)blockIdx.z * strC;
                *(float2*)&Cz[(size_t)rowA * ldc + col] = make_float2(lox, loy);
                *(float2*)&Cz[(size_t)rowB * ldc + col] = make_float2(hix, hiy);
            } else if (mode == 1) {
                const int h = col >> 6, tc = col & 63;
                *(float2*)&C[((size_t)h * SQ + rowA) * HD + tc] = make_float2(lox, loy);
                *(float2*)&C[((size_t)h * SQ + rowB) * HD + tc] = make_float2(hix, hiy);
            } else {
                const int h = col >> 6, tc = col & 63;
                __nv_bfloat16 h0,h1,h2,h3,l0,l1,l2,l3;
                bsplit(lox, h0, l0); bsplit(loy, h1, l1);
                bsplit(hix, h2, l2); bsplit(hiy, h3, l3);
                *(__nv_bfloat162*)&Ch[((size_t)h * SQ + rowA) * HD + tc] = __nv_bfloat162(h0, h1);
                *(__nv_bfloat162*)&Cl[((size_t)h * SQ + rowA) * HD + tc] = __nv_bfloat162(l0, l1);
                *(__nv_bfloat162*)&Ch[((size_t)h * SQ + rowB) * HD + tc] = __nv_bfloat162(h2, h3);
                *(__nv_bfloat162*)&Cl[((size_t)h * SQ + rowB) * HD + tc] = __nv_bfloat162(l2, l3);
            }
        }
    }
#undef STAGE
}

// ============================================================
// Per-head V column sums
// ============================================================
__global__ __launch_bounds__(256) void vsum_kernel()
{
    const int h = blockIdx.x;
    const int t = threadIdx.x & 63;
    const int g = threadIdx.x >> 6;
    const float* Vh = g_V + (size_t)h * SQ * HD;
    float s = 0.0f;
    for (int r = g * 512; r < (g + 1) * 512; ++r)
        s += Vh[(size_t)r * HD + t];
    __shared__ float red[4][64];
    red[g][t] = s;
    __syncthreads();
    if (g == 0)
        g_vsum[h * HD + t] = red[0][t] + red[1][t] + red[2][t] + red[3][t];
}

// ============================================================
// Top-16 + sparse softmax + PV gather. One warp per (h, q).
// (unchanged from the 966us kernel)
// ============================================================
__global__ __launch_bounds__(128) void topk_attend()
{
    const unsigned FULL = 0xffffffffu;
    const int gwarp = (blockIdx.x * 128 + threadIdx.x) >> 5;
    const int lane  = threadIdx.x & 31;
    const int h = gwarp >> 11;
    const int q = gwarp & 2047;

    const float* row = g_scores + ((size_t)h * SQ + q) * SQ;

    float lv[16];
    int   li[16];
#pragma unroll
    for (int i = 0; i < 16; i++) { lv[i] = -1e30f; li[i] = 0; }

#pragma unroll 4
    for (int c = 0; c < 16; c++) {
        const int base = c * 128 + lane * 4;
        float4 v4 = *(const float4*)&row[base];
        float vals[4] = {v4.x, v4.y, v4.z, v4.w};
#pragma unroll
        for (int j = 0; j < 4; j++) {
            const float val = vals[j];
            if (val > lv[15]) {
                lv[15] = val; li[15] = base + j;
#pragma unroll
                for (int p = 15; p >= 1; --p) {
                    if (lv[p] > lv[p - 1]) {
                        float tv = lv[p]; lv[p] = lv[p - 1]; lv[p - 1] = tv;
                        int   ti = li[p]; li[p] = li[p - 1]; li[p - 1] = ti;
                    }
                }
            }
        }
    }

    float fv = -1e30f;
    int   fi = 0;
    for (int r = 0; r < 16; r++) {
        float bv = lv[0]; int bi = li[0]; int bl = lane;
#pragma unroll
        for (int off = 16; off > 0; off >>= 1) {
            float ov = __shfl_down_sync(FULL, bv, off);
            int   oi = __shfl_down_sync(FULL, bi, off);
            int   ol = __shfl_down_sync(FULL, bl, off);
            if (ov > bv) { bv = ov; bi = oi; bl = ol; }
        }
        bv = __shfl_sync(FULL, bv, 0);
        bi = __shfl_sync(FULL, bi, 0);
        bl = __shfl_sync(FULL, bl, 0);
        if (lane == bl) {
#pragma unroll
            for (int p = 0; p < 15; p++) { lv[p] = lv[p + 1]; li[p] = li[p + 1]; }
            lv[15] = -1e30f;
        }
        if (lane == r) { fv = bv; fi = bi; }
    }

    float m = __shfl_sync(FULL, fv, 0);
    m = fmaxf(m, 0.0f);
    float e = (lane < 16) ? expf(fv - m) : 0.0f;
    float z = e;
#pragma unroll
    for (int off = 16; off > 0; off >>= 1)
        z += __shfl_xor_sync(FULL, z, off);
    const float e0 = expf(-m);
    const float Z  = z + (float)(SQ - FACT) * e0;
    const float p0 = e0 / Z;
    const float w  = e / Z - p0;

    const float* Vh = g_V + (size_t)h * SQ * HD;
    float acc0 = p0 * g_vsum[h * HD + lane];
    float acc1 = p0 * g_vsum[h * HD + lane + 32];
#pragma unroll
    for (int i = 0; i < 16; i++) {
        const float wi  = __shfl_sync(FULL, w,  i);
        const int   idx = __shfl_sync(FULL, fi, i);
        const float* vr = Vh + (size_t)idx * HD;
        acc0 = fmaf(wi, vr[lane],      acc0);
        acc1 = fmaf(wi, vr[lane + 32], acc1);
    }
    float* o = g_attn + (size_t)q * DIM + h * HD;
    o[lane]      = acc0;
    o[lane + 32] = acc1;
}

// ============================================================
extern "C" void kernel_launch(void* const* d_in, const int* in_sizes, int n_in,
                              void* d_out, int out_size)
{
    const float* x  = (const float*)d_in[0];
    const float* Wq = (const float*)d_in[1];
    const float* bq = (const float*)d_in[2];
    const float* Wk = (const float*)d_in[3];
    const float* bk = (const float*)d_in[4];
    const float* Wv = (const float*)d_in[5];
    const float* bv = (const float*)d_in[6];
    const float* Wo = (const float*)d_in[7];
    const float* bo = (const float*)d_in[8];
    float* out = (float*)d_out;

    float *Vp, *attnp, *scoresp;
    __nv_bfloat16 *xh, *xl, *ath, *atl, *WTh, *WTl, *Qh, *Ql, *Kh, *Kl;
    cudaGetSymbolAddress((void**)&Vp,      g_V);
    cudaGetSymbolAddress((void**)&attnp,   g_attn);
    cudaGetSymbolAddress((void**)&scoresp, g_scores);
    cudaGetSymbolAddress((void**)&xh,  g_xh);  cudaGetSymbolAddress((void**)&xl,  g_xl);
    cudaGetSymbolAddress((void**)&ath, g_ath); cudaGetSymbolAddress((void**)&atl, g_atl);
    cudaGetSymbolAddress((void**)&WTh, g_WTh); cudaGetSymbolAddress((void**)&WTl, g_WTl);
    cudaGetSymbolAddress((void**)&Qh,  g_Qh);  cudaGetSymbolAddress((void**)&Ql,  g_Ql);
    cudaGetSymbolAddress((void**)&Kh,  g_Kh);  cudaGetSymbolAddress((void**)&Kl,  g_Kl);

    static int smem_set = 0;
    if (!smem_set) {
        cudaFuncSetAttribute(nt_bf16x3_gemm,
                             cudaFuncAttributeMaxDynamicSharedMemorySize,
                             GSMEM_BYTES);
        smem_set = 1;
    }

    const size_t DD = (size_t)DIM * DIM;

    dim3 gT(DIM / 32, DIM / 32);
    dim3 bT(32, 8);
    transpose_split<<<gT, bT>>>(Wq, WTh,          WTl);
    transpose_split<<<gT, bT>>>(Wk, WTh + DD,     WTl + DD);
    transpose_split<<<gT, bT>>>(Wv, WTh + 2 * DD, WTl + 2 * DD);
    transpose_split<<<gT, bT>>>(Wo, WTh + 3 * DD, WTl + 3 * DD);

    split_convert<<<(SQ * DIM / 4 + 255) / 256, 256>>>(x, xh, xl, SQ * DIM / 4);

    dim3 gProj(DIM / 128, SQ / 128, 1);
    // Q projection -> bf16 split planes
    nt_bf16x3_gemm<<<gProj, 256, GSMEM_BYTES>>>(
        xh, xl, WTh, WTl, bq, nullptr, Qh, Ql,
        DIM, DIM, DIM, DIM, 1.0f, 2, 0, 0, 0);
    // K projection -> bf16 split planes
    nt_bf16x3_gemm<<<gProj, 256, GSMEM_BYTES>>>(
        xh, xl, WTh + DD, WTl + DD, bk, nullptr, Kh, Kl,
        DIM, DIM, DIM, DIM, 1.0f, 2, 0, 0, 0);
    // V projection -> fp32 remap
    nt_bf16x3_gemm<<<gProj, 256, GSMEM_BYTES>>>(
        xh, xl, WTh + 2 * DD, WTl + 2 * DD, bv, Vp, nullptr, nullptr,
        DIM, DIM, DIM, DIM, 1.0f, 1, 0, 0, 0);

    vsum_kernel<<<NH, 256>>>();

    // scores: per-head NT GEMM over bf16 planes
    dim3 gSc(SQ / 128, SQ / 128, NH);
    nt_bf16x3_gemm<<<gSc, 256, GSMEM_BYTES>>>(
        Qh, Ql, Kh, Kl, nullptr, scoresp, nullptr, nullptr,
        HD, HD, HD, SQ, 0.125f, 0,
        (long)SQ * HD, (long)SQ * HD, (long)SQ * SQ);

    topk_attend<<<(NH * SQ) / 4, 128>>>();

    split_convert<<<(SQ * DIM / 4 + 255) / 256, 256>>>(attnp, ath, atl, SQ * DIM / 4);

    // output projection -> fp32 out
    nt_bf16x3_gemm<<<gProj, 256, GSMEM_BYTES>>>(
        ath, atl, WTh + 3 * DD, WTl + 3 * DD, bo, out, nullptr, nullptr,
        DIM, DIM, DIM, DIM, 1.0f, 0, 0, 0, 0);
}